// round 11
// baseline (speedup 1.0000x reference)
#include <cuda_runtime.h>
#include <cuda_bf16.h>
#include <math.h>
#include <stdint.h>

#define DIM     1024
#define HEADS   16
#define DHEAD   64
#define INNER   1024
#define BATCH   4
#define NTOK    4096
#define MTOT    (BATCH * NTOK)      // 16384
#define QKVN    (3 * INNER)         // 3072
#define NSPLIT  16

// ---------------------------------------------------------------------------
// Scratch (device globals; no runtime allocation allowed)
// ---------------------------------------------------------------------------
__device__ float g_qkv[(size_t)MTOT * QKVN];                                 // 192 MB
__device__ float g_part[(size_t)NSPLIT * BATCH * HEADS * DHEAD * DHEAD];     // 16 MB
__device__ float g_C[(size_t)BATCH * HEADS * DHEAD * DHEAD];                 // 1 MB

// Packed bf16 hi/lo (row-major A [M][K]; transposed B [N][K])
__device__ __nv_bfloat16 g_xh[(size_t)MTOT * DIM];
__device__ __nv_bfloat16 g_xl[(size_t)MTOT * DIM];
__device__ __nv_bfloat16 g_uh[(size_t)MTOT * DIM];
__device__ __nv_bfloat16 g_ul[(size_t)MTOT * DIM];
__device__ __nv_bfloat16 g_wqh[(size_t)QKVN * DIM];   // [N=3072][K=1024]
__device__ __nv_bfloat16 g_wql[(size_t)QKVN * DIM];
__device__ __nv_bfloat16 g_woh[(size_t)INNER * DIM];  // [N=1024][K=1024]
__device__ __nv_bfloat16 g_wol[(size_t)INNER * DIM];

// ---------------------------------------------------------------------------
// helpers
// ---------------------------------------------------------------------------
__device__ __forceinline__ uint32_t smem_u32(const void* p) {
    uint32_t a;
    asm("{ .reg .u64 t; cvta.to.shared.u64 t, %1; cvt.u32.u64 %0, t; }"
        : "=r"(a) : "l"(p));
    return a;
}

__device__ __forceinline__ void cp_async16(uint32_t dst, const void* src) {
    asm volatile("cp.async.cg.shared.global [%0], [%1], 16;"
                 :: "r"(dst), "l"(src) : "memory");
}
__device__ __forceinline__ void cp_commit() {
    asm volatile("cp.async.commit_group;" ::: "memory");
}
template <int N>
__device__ __forceinline__ void cp_wait() {
    asm volatile("cp.async.wait_group %0;" :: "n"(N) : "memory");
}

__device__ __forceinline__ void ldm_x4(uint32_t& r0, uint32_t& r1,
                                       uint32_t& r2, uint32_t& r3, uint32_t a) {
    asm volatile("ldmatrix.sync.aligned.m8n8.x4.shared.b16 {%0,%1,%2,%3}, [%4];"
                 : "=r"(r0), "=r"(r1), "=r"(r2), "=r"(r3) : "r"(a));
}

__device__ __forceinline__ void mma_bf16(float& c0, float& c1, float& c2, float& c3,
                                         uint32_t a0, uint32_t a1, uint32_t a2, uint32_t a3,
                                         uint32_t b0, uint32_t b1) {
    asm volatile(
        "mma.sync.aligned.m16n8k16.row.col.f32.bf16.bf16.f32 "
        "{%0,%1,%2,%3}, {%4,%5,%6,%7}, {%8,%9}, {%0,%1,%2,%3};"
        : "+f"(c0), "+f"(c1), "+f"(c2), "+f"(c3)
        : "r"(a0), "r"(a1), "r"(a2), "r"(a3), "r"(b0), "r"(b1));
}

__device__ __forceinline__ void split_bf16(float f, ushort& h, ushort& l) {
    __nv_bfloat16 hi = __float2bfloat16(f);
    __nv_bfloat16 lo = __float2bfloat16(f - __bfloat162float(hi));
    h = __bfloat16_as_ushort(hi);
    l = __bfloat16_as_ushort(lo);
}

// ---------------------------------------------------------------------------
// bf16x3 GEMM via mma.sync: C[M,N] = A @ B^T (+bias)
// CTA tile 128x128, BK=32, 8 warps (4m x 2n). 2 CTAs/SM.
// Inner loop issues MMAs in 3 passes of 8 independent MMAs each so dependent
// HMMAs to the same accumulator are >= 8 issue slots apart (RAW hidden).
// ---------------------------------------------------------------------------
#define BKC      32
#define ROWB     80                      // padded row bytes (40 bf16)
#define OPSZ     (128 * ROWB)            // 10240 B per operand tile
#define BUFSZ    (4 * OPSZ)              // 40960 B per buffer
#define GEMM_SMEM (2 * BUFSZ)            // 81920 B

__global__ __launch_bounds__(256, 2) void gemm_bf16x3_kernel(
    const __nv_bfloat16* __restrict__ Ah, const __nv_bfloat16* __restrict__ Al,
    const __nv_bfloat16* __restrict__ Bth, const __nv_bfloat16* __restrict__ Btl,
    float* __restrict__ C, const float* __restrict__ bias, int N, int K)
{
    extern __shared__ char smem[];
    const uint32_t sb = smem_u32(smem);
    const int tid = threadIdx.x;
    const int lane = tid & 31;
    const int wid = tid >> 5;
    const int wm = wid & 3;          // 0..3  (m)
    const int wn = wid >> 2;         // 0..1  (n)
    const int ntile = blockIdx.x;
    const int mtile = blockIdx.y;

    // ---- gmem -> smem assignment (cp.async, 16B each, 8 per thread/chunk)
    const int g = tid >> 6;          // operand 0..3 (Ah, Al, Bth, Btl)
    const int lt = tid & 63;
    const __nv_bfloat16* opsrc;
    if (g == 0)      opsrc = Ah  + (size_t)mtile * 128 * K;
    else if (g == 1) opsrc = Al  + (size_t)mtile * 128 * K;
    else if (g == 2) opsrc = Bth + (size_t)ntile * 128 * K;
    else             opsrc = Btl + (size_t)ntile * 128 * K;

    const int nchunks = K / BKC;

    auto issue_chunk = [&](int c, int buf) {
        const uint32_t dbase = sb + buf * BUFSZ + g * OPSZ;
#pragma unroll
        for (int i = 0; i < 8; i++) {
            int idx = lt + 64 * i;       // 0..511
            int row = idx >> 2;
            int seg = idx & 3;
            cp_async16(dbase + row * ROWB + seg * 16,
                       opsrc + (size_t)row * K + c * BKC + seg * 8);
        }
        cp_commit();
    };

    float acc[2][8][4];
#pragma unroll
    for (int im = 0; im < 2; im++)
#pragma unroll
        for (int jn = 0; jn < 8; jn++)
#pragma unroll
            for (int r = 0; r < 4; r++) acc[im][jn][r] = 0.f;

    const int at_tile = lane >> 3;
    const int a_row = (at_tile & 1) * 8 + (lane & 7);
    const int a_cadd = (at_tile >> 1) * 16;
    const int b_row = ((at_tile >> 1) * 8) + (lane & 7);
    const int b_cadd = (at_tile & 1) * 16;

    issue_chunk(0, 0);

    for (int c = 0; c < nchunks; c++) {
        const int buf = c & 1;
        if (c + 1 < nchunks) { issue_chunk(c + 1, buf ^ 1); cp_wait<1>(); }
        else                 { cp_wait<0>(); }
        __syncthreads();

        const uint32_t base = sb + buf * BUFSZ;
#pragma unroll
        for (int kk = 0; kk < 2; kk++) {
            const int kb = kk * 32;  // 16 elems = 32 bytes
            uint32_t ah[2][4], al[2][4];
#pragma unroll
            for (int im = 0; im < 2; im++) {
                uint32_t aoff = (uint32_t)(wm * 32 + im * 16 + a_row) * ROWB + kb + a_cadd;
                ldm_x4(ah[im][0], ah[im][1], ah[im][2], ah[im][3], base + 0 * OPSZ + aoff);
                ldm_x4(al[im][0], al[im][1], al[im][2], al[im][3], base + 1 * OPSZ + aoff);
            }
#pragma unroll
            for (int pg = 0; pg < 2; pg++) {
                uint32_t bh[2][4], bl[2][4];
#pragma unroll
                for (int pp = 0; pp < 2; pp++) {
                    const int p = pg * 2 + pp;
                    uint32_t boff = (uint32_t)(wn * 64 + p * 16 + b_row) * ROWB + kb + b_cadd;
                    ldm_x4(bh[pp][0], bh[pp][1], bh[pp][2], bh[pp][3], base + 2 * OPSZ + boff);
                    ldm_x4(bl[pp][0], bl[pp][1], bl[pp][2], bl[pp][3], base + 3 * OPSZ + boff);
                }
                // pass 1: hi*hi — 8 independent accumulators
#pragma unroll
                for (int pp = 0; pp < 2; pp++)
#pragma unroll
                    for (int im = 0; im < 2; im++)
#pragma unroll
                        for (int q2 = 0; q2 < 2; q2++) {
                            float* cc = acc[im][(pg * 2 + pp) * 2 + q2];
                            mma_bf16(cc[0], cc[1], cc[2], cc[3],
                                     ah[im][0], ah[im][1], ah[im][2], ah[im][3],
                                     bh[pp][q2 * 2], bh[pp][q2 * 2 + 1]);
                        }
                // pass 2: hi*lo
#pragma unroll
                for (int pp = 0; pp < 2; pp++)
#pragma unroll
                    for (int im = 0; im < 2; im++)
#pragma unroll
                        for (int q2 = 0; q2 < 2; q2++) {
                            float* cc = acc[im][(pg * 2 + pp) * 2 + q2];
                            mma_bf16(cc[0], cc[1], cc[2], cc[3],
                                     ah[im][0], ah[im][1], ah[im][2], ah[im][3],
                                     bl[pp][q2 * 2], bl[pp][q2 * 2 + 1]);
                        }
                // pass 3: lo*hi
#pragma unroll
                for (int pp = 0; pp < 2; pp++)
#pragma unroll
                    for (int im = 0; im < 2; im++)
#pragma unroll
                        for (int q2 = 0; q2 < 2; q2++) {
                            float* cc = acc[im][(pg * 2 + pp) * 2 + q2];
                            mma_bf16(cc[0], cc[1], cc[2], cc[3],
                                     al[im][0], al[im][1], al[im][2], al[im][3],
                                     bh[pp][q2 * 2], bh[pp][q2 * 2 + 1]);
                        }
            }
        }
        __syncthreads();
    }

    // ---- epilogue
    const int m0 = mtile * 128 + wm * 32;
    const int n0 = ntile * 128 + wn * 64;
#pragma unroll
    for (int im = 0; im < 2; im++) {
#pragma unroll
        for (int jn = 0; jn < 8; jn++) {
            const int row = m0 + im * 16 + (lane >> 2);
            const int col = n0 + jn * 8 + (lane & 3) * 2;
            float b0 = bias ? bias[col] : 0.f;
            float b1 = bias ? bias[col + 1] : 0.f;
            float2 v0 = {acc[im][jn][0] + b0, acc[im][jn][1] + b1};
            float2 v1 = {acc[im][jn][2] + b0, acc[im][jn][3] + b1};
            *reinterpret_cast<float2*>(C + (size_t)row * N + col) = v0;
            *reinterpret_cast<float2*>(C + (size_t)(row + 8) * N + col) = v1;
        }
    }
}

// ---------------------------------------------------------------------------
// packA: fp32 [M][K] -> hi/lo bf16 [M][K] (row-major). 8 elems/thread.
// ---------------------------------------------------------------------------
__global__ __launch_bounds__(256) void packA_kernel(
    const float* __restrict__ A, __nv_bfloat16* __restrict__ H,
    __nv_bfloat16* __restrict__ L)
{
    const size_t e0 = ((size_t)blockIdx.x * 256 + threadIdx.x) * 8;
    float4 v0 = *reinterpret_cast<const float4*>(A + e0);
    float4 v1 = *reinterpret_cast<const float4*>(A + e0 + 4);
    float f[8] = {v0.x, v0.y, v0.z, v0.w, v1.x, v1.y, v1.z, v1.w};
    ushort h[8], l[8];
#pragma unroll
    for (int i = 0; i < 8; i++) split_bf16(f[i], h[i], l[i]);
    *reinterpret_cast<uint4*>(H + e0) = *reinterpret_cast<uint4*>(h);
    *reinterpret_cast<uint4*>(L + e0) = *reinterpret_cast<uint4*>(l);
}

// ---------------------------------------------------------------------------
// packBt: fp32 W[K][N] -> hi/lo bf16 Bt[N][K] (transpose). 32x32 tiles.
// ---------------------------------------------------------------------------
__global__ __launch_bounds__(256) void packBt_kernel(
    const float* __restrict__ W, __nv_bfloat16* __restrict__ H,
    __nv_bfloat16* __restrict__ L, int N, int K)
{
    __shared__ float tile[32][33];
    const int k0 = blockIdx.x * 32;
    const int n0 = blockIdx.y * 32;
    const int x = threadIdx.x, y = threadIdx.y;  // block (32, 8)

#pragma unroll
    for (int r = 0; r < 4; r++) {
        int row = y + r * 8;
        tile[row][x] = W[(size_t)(k0 + row) * N + n0 + x];
    }
    __syncthreads();
#pragma unroll
    for (int r = 0; r < 4; r++) {
        int n = y + r * 8;
        float f = tile[x][n];
        ushort h, l;
        split_bf16(f, h, l);
        size_t o = (size_t)(n0 + n) * K + k0 + x;
        H[o] = __ushort_as_bfloat16(h);
        L[o] = __ushort_as_bfloat16(l);
    }
}

// ---------------------------------------------------------------------------
// kv partial: kv[d][e] = sum_n k[n,d]*v[n,e] per (b,h,split)
// cp.async double-buffered, NSPLIT=16 (256 tokens/block).
// ---------------------------------------------------------------------------
#define KVCH 16

__global__ __launch_bounds__(256) void kv_partial_kernel(float* __restrict__ part)
{
    const int bh = blockIdx.x;
    const int split = blockIdx.y;
    const int b = bh / HEADS, h = bh % HEADS;
    const int n0 = split * (NTOK / NSPLIT);
    const int nstages = (NTOK / NSPLIT) / KVCH;

    __shared__ float ks[2][KVCH][DHEAD];
    __shared__ float vs[2][KVCH][DHEAD];

    const int tid = threadIdx.x;
    const int tx = tid % 16, ty = tid / 16;

    const float* base = g_qkv + (size_t)b * NTOK * QKVN;

    const int li = tid * 4;
    const int lr = li / DHEAD, lc = li % DHEAD;
    const uint32_t ks_a[2] = {smem_u32(&ks[0][lr][lc]), smem_u32(&ks[1][lr][lc])};
    const uint32_t vs_a[2] = {smem_u32(&vs[0][lr][lc]), smem_u32(&vs[1][lr][lc])};

    auto issue = [&](int s, int buf) {
        const float* p = base + (size_t)(n0 + s * KVCH + lr) * QKVN + h * DHEAD + lc;
        cp_async16(ks_a[buf], p + INNER);
        cp_async16(vs_a[buf], p + 2 * INNER);
        cp_commit();
    };

    float acc[4][4];
#pragma unroll
    for (int i = 0; i < 4; i++)
#pragma unroll
        for (int j = 0; j < 4; j++) acc[i][j] = 0.f;

    issue(0, 0);

    for (int s = 0; s < nstages; s++) {
        const int buf = s & 1;
        if (s + 1 < nstages) { issue(s + 1, buf ^ 1); cp_wait<1>(); }
        else                 { cp_wait<0>(); }
        __syncthreads();

#pragma unroll
        for (int nn = 0; nn < KVCH; nn++) {
            float rk[4], rv[4];
#pragma unroll
            for (int i = 0; i < 4; i++) rk[i] = ks[buf][nn][ty * 4 + i];
#pragma unroll
            for (int j = 0; j < 4; j++) rv[j] = vs[buf][nn][tx * 4 + j];
#pragma unroll
            for (int i = 0; i < 4; i++)
#pragma unroll
                for (int j = 0; j < 4; j++)
                    acc[i][j] += rk[i] * rv[j];
        }
        __syncthreads();
    }

    float* out = part + ((size_t)split * BATCH * HEADS + bh) * (DHEAD * DHEAD);
#pragma unroll
    for (int i = 0; i < 4; i++)
#pragma unroll
        for (int j = 0; j < 4; j++)
            out[(ty * 4 + i) * DHEAD + tx * 4 + j] = acc[i][j];
}

// ---------------------------------------------------------------------------
// kv finalize: C[d][e] = gamma_h^2 * kv[d][e] / ||kv[d,:]||
// ---------------------------------------------------------------------------
__global__ void kv_finalize_kernel(const float* __restrict__ gamma)
{
    const int bh = blockIdx.x;
    const int d = threadIdx.x;
    const int h = bh % HEADS;

    float row[DHEAD];
#pragma unroll
    for (int e = 0; e < DHEAD; e++) row[e] = 0.f;

    for (int s = 0; s < NSPLIT; s++) {
        const float* p = g_part + ((size_t)s * BATCH * HEADS + bh) * (DHEAD * DHEAD) + d * DHEAD;
#pragma unroll
        for (int e = 0; e < DHEAD; e++) row[e] += p[e];
    }
    float ss = 0.f;
#pragma unroll
    for (int e = 0; e < DHEAD; e++) ss += row[e] * row[e];

    const float g = gamma[h];
    const float scale = g * g / sqrtf(ss);

    float* out = g_C + (size_t)bh * DHEAD * DHEAD + d * DHEAD;
#pragma unroll
    for (int e = 0; e < DHEAD; e++) out[e] = row[e] * scale;
}

// ---------------------------------------------------------------------------
// apply: u = (q @ C) / ||q||, emits bf16 hi/lo streams for GEMM2 directly.
// ---------------------------------------------------------------------------
#define QPAD 68

__global__ __launch_bounds__(256) void apply_kernel(
    __nv_bfloat16* __restrict__ UH, __nv_bfloat16* __restrict__ UL)
{
    const int bh = blockIdx.x;
    const int chunk = blockIdx.y;
    const int b = bh / HEADS, h = bh % HEADS;

    __shared__ float Cs[DHEAD][DHEAD];
    __shared__ float qs[64][QPAD];
    __shared__ float inv[64];

    const int tid = threadIdx.x;
    const int n0 = chunk * 64;

#pragma unroll
    for (int i = tid * 4; i < DHEAD * DHEAD; i += 1024)
        *reinterpret_cast<float4*>(&Cs[0][0] + i) =
            *reinterpret_cast<const float4*>(g_C + (size_t)bh * DHEAD * DHEAD + i);

#pragma unroll
    for (int i = tid * 4; i < 64 * DHEAD; i += 1024) {
        int t = i / DHEAD, d = i % DHEAD;
        *reinterpret_cast<float4*>(&qs[t][d]) =
            *reinterpret_cast<const float4*>(g_qkv + (size_t)(b * NTOK + n0 + t) * QKVN + h * DHEAD + d);
    }
    __syncthreads();

    if (tid < 64) {
        float ss = 0.f;
#pragma unroll
        for (int d = 0; d < DHEAD; d++) { float x = qs[tid][d]; ss += x * x; }
        inv[tid] = 1.0f / sqrtf(ss);
    }
    __syncthreads();

    const int tx = tid % 16, ty = tid / 16;
    float acc[4][4];
#pragma unroll
    for (int i = 0; i < 4; i++)
#pragma unroll
        for (int j = 0; j < 4; j++) acc[i][j] = 0.f;

#pragma unroll
    for (int d = 0; d < DHEAD; d++) {
        float rq[4], rc[4];
#pragma unroll
        for (int i = 0; i < 4; i++) rq[i] = qs[ty * 4 + i][d];
#pragma unroll
        for (int j = 0; j < 4; j++) rc[j] = Cs[d][tx * 4 + j];
#pragma unroll
        for (int i = 0; i < 4; i++)
#pragma unroll
            for (int j = 0; j < 4; j++)
                acc[i][j] += rq[i] * rc[j];
    }

#pragma unroll
    for (int i = 0; i < 4; i++) {
        int t = ty * 4 + i;
        float s = inv[t];
        ushort hh[4], ll[4];
#pragma unroll
        for (int j = 0; j < 4; j++) split_bf16(acc[i][j] * s, hh[j], ll[j]);
        size_t o = (size_t)(b * NTOK + n0 + t) * INNER + h * DHEAD + tx * 4;
        *reinterpret_cast<uint2*>(UH + o) = *reinterpret_cast<uint2*>(hh);
        *reinterpret_cast<uint2*>(UL + o) = *reinterpret_cast<uint2*>(ll);
    }
}

// ---------------------------------------------------------------------------
extern "C" void kernel_launch(void* const* d_in, const int* in_sizes, int n_in,
                              void* d_out, int out_size)
{
    const float* x     = (const float*)d_in[0];
    const float* W_qkv = (const float*)d_in[1];
    const float* W_o   = (const float*)d_in[2];
    const float* b_o   = (const float*)d_in[3];
    const float* gamma = (const float*)d_in[4];
    float* out = (float*)d_out;

    static float* qkv_p = nullptr;
    static float* part_p = nullptr;
    static __nv_bfloat16 *xh, *xl, *uh, *ul, *wqh, *wql, *woh, *wol;
    if (!qkv_p) {
        cudaGetSymbolAddress((void**)&qkv_p, g_qkv);
        cudaGetSymbolAddress((void**)&part_p, g_part);
        cudaGetSymbolAddress((void**)&xh, g_xh);
        cudaGetSymbolAddress((void**)&xl, g_xl);
        cudaGetSymbolAddress((void**)&uh, g_uh);
        cudaGetSymbolAddress((void**)&ul, g_ul);
        cudaGetSymbolAddress((void**)&wqh, g_wqh);
        cudaGetSymbolAddress((void**)&wql, g_wql);
        cudaGetSymbolAddress((void**)&woh, g_woh);
        cudaGetSymbolAddress((void**)&wol, g_wol);
        cudaFuncSetAttribute(gemm_bf16x3_kernel,
                             cudaFuncAttributeMaxDynamicSharedMemorySize, GEMM_SMEM);
    }

    // 1) pack x and W_qkv
    packA_kernel<<<(size_t)MTOT * DIM / 2048, 256>>>(x, xh, xl);
    packBt_kernel<<<dim3(DIM / 32, QKVN / 32), dim3(32, 8)>>>(W_qkv, wqh, wql, QKVN, DIM);

    // 2) qkv = x @ W_qkv  (bf16x3 mma.sync)
    gemm_bf16x3_kernel<<<dim3(QKVN / 128, MTOT / 128), 256, GEMM_SMEM>>>(
        xh, xl, wqh, wql, qkv_p, nullptr, QKVN, DIM);

    // 3) kv partials, finalize, apply (apply emits packed u directly)
    kv_partial_kernel<<<dim3(BATCH * HEADS, NSPLIT), 256>>>(part_p);
    kv_finalize_kernel<<<BATCH * HEADS, DHEAD>>>(gamma);
    apply_kernel<<<dim3(BATCH * HEADS, NTOK / 64), 256>>>(uh, ul);

    // 4) pack W_o
    packBt_kernel<<<dim3(DIM / 32, INNER / 32), dim3(32, 8)>>>(W_o, woh, wol, INNER, DIM);

    // 5) out = u @ W_o + b_o  (bf16x3 mma.sync)
    gemm_bf16x3_kernel<<<dim3(INNER / 128, MTOT / 128), 256, GEMM_SMEM>>>(
        uh, ul, woh, wol, out, b_o, INNER, DIM);
}

// round 12
// speedup vs baseline: 1.0778x; 1.0778x over previous
#include <cuda_runtime.h>
#include <cuda_bf16.h>
#include <math.h>
#include <stdint.h>

#define DIM     1024
#define HEADS   16
#define DHEAD   64
#define INNER   1024
#define BATCH   4
#define NTOK    4096
#define MTOT    (BATCH * NTOK)      // 16384
#define QKVN    (3 * INNER)         // 3072
#define NSPLIT  16

// ---------------------------------------------------------------------------
// Scratch (device globals; no runtime allocation allowed)
// ---------------------------------------------------------------------------
__device__ float g_qkv[(size_t)MTOT * QKVN];                                 // 192 MB
__device__ float g_part[(size_t)NSPLIT * BATCH * HEADS * DHEAD * DHEAD];     // 16 MB
__device__ float g_C[(size_t)BATCH * HEADS * DHEAD * DHEAD];                 // 1 MB

// Packed bf16 hi/lo (row-major A [M][K]; transposed B [N][K])
__device__ __nv_bfloat16 g_xh[(size_t)MTOT * DIM];
__device__ __nv_bfloat16 g_xl[(size_t)MTOT * DIM];
__device__ __nv_bfloat16 g_uh[(size_t)MTOT * DIM];
__device__ __nv_bfloat16 g_ul[(size_t)MTOT * DIM];
__device__ __nv_bfloat16 g_wqh[(size_t)QKVN * DIM];   // [N=3072][K=1024]
__device__ __nv_bfloat16 g_wql[(size_t)QKVN * DIM];
__device__ __nv_bfloat16 g_woh[(size_t)INNER * DIM];  // [N=1024][K=1024]
__device__ __nv_bfloat16 g_wol[(size_t)INNER * DIM];

// ---------------------------------------------------------------------------
// helpers
// ---------------------------------------------------------------------------
__device__ __forceinline__ uint32_t smem_u32(const void* p) {
    uint32_t a;
    asm("{ .reg .u64 t; cvta.to.shared.u64 t, %1; cvt.u32.u64 %0, t; }"
        : "=r"(a) : "l"(p));
    return a;
}

__device__ __forceinline__ void cp_async16(uint32_t dst, const void* src) {
    asm volatile("cp.async.cg.shared.global [%0], [%1], 16;"
                 :: "r"(dst), "l"(src) : "memory");
}
__device__ __forceinline__ void cp_commit() {
    asm volatile("cp.async.commit_group;" ::: "memory");
}
template <int N>
__device__ __forceinline__ void cp_wait() {
    asm volatile("cp.async.wait_group %0;" :: "n"(N) : "memory");
}

__device__ __forceinline__ void ldm_x4(uint32_t& r0, uint32_t& r1,
                                       uint32_t& r2, uint32_t& r3, uint32_t a) {
    asm volatile("ldmatrix.sync.aligned.m8n8.x4.shared.b16 {%0,%1,%2,%3}, [%4];"
                 : "=r"(r0), "=r"(r1), "=r"(r2), "=r"(r3) : "r"(a));
}

__device__ __forceinline__ void mma_bf16(float& c0, float& c1, float& c2, float& c3,
                                         uint32_t a0, uint32_t a1, uint32_t a2, uint32_t a3,
                                         uint32_t b0, uint32_t b1) {
    asm volatile(
        "mma.sync.aligned.m16n8k16.row.col.f32.bf16.bf16.f32 "
        "{%0,%1,%2,%3}, {%4,%5,%6,%7}, {%8,%9}, {%0,%1,%2,%3};"
        : "+f"(c0), "+f"(c1), "+f"(c2), "+f"(c3)
        : "r"(a0), "r"(a1), "r"(a2), "r"(a3), "r"(b0), "r"(b1));
}

__device__ __forceinline__ void split_bf16(float f, ushort& h, ushort& l) {
    __nv_bfloat16 hi = __float2bfloat16(f);
    __nv_bfloat16 lo = __float2bfloat16(f - __bfloat162float(hi));
    h = __bfloat16_as_ushort(hi);
    l = __bfloat16_as_ushort(lo);
}

// ---------------------------------------------------------------------------
// GEMM body (device function): C[M,N] tile (mtile,ntile) of A @ B^T (+bias)
// CTA tile 128x128, BK=32, 8 warps (4m x 2n). Single __syncthreads per chunk.
// ---------------------------------------------------------------------------
#define BKC      32
#define ROWB     80                      // padded row bytes (40 bf16)
#define OPSZ     (128 * ROWB)            // 10240 B per operand tile
#define BUFSZ    (4 * OPSZ)              // 40960 B per buffer
#define GEMM_SMEM (2 * BUFSZ)            // 81920 B

__device__ __forceinline__ void gemm_body(
    char* smem, int mtile, int ntile,
    const __nv_bfloat16* __restrict__ Ah, const __nv_bfloat16* __restrict__ Al,
    const __nv_bfloat16* __restrict__ Bth, const __nv_bfloat16* __restrict__ Btl,
    float* __restrict__ C, const float* __restrict__ bias, int N, int K)
{
    const uint32_t sb = smem_u32(smem);
    const int tid = threadIdx.x;
    const int lane = tid & 31;
    const int wid = tid >> 5;
    const int wm = wid & 3;          // 0..3  (m)
    const int wn = wid >> 2;         // 0..1  (n)

    const int g = tid >> 6;          // operand 0..3 (Ah, Al, Bth, Btl)
    const int lt = tid & 63;
    const __nv_bfloat16* opsrc;
    if (g == 0)      opsrc = Ah  + (size_t)mtile * 128 * K;
    else if (g == 1) opsrc = Al  + (size_t)mtile * 128 * K;
    else if (g == 2) opsrc = Bth + (size_t)ntile * 128 * K;
    else             opsrc = Btl + (size_t)ntile * 128 * K;

    const int nchunks = K / BKC;

    auto issue_chunk = [&](int c, int buf) {
        const uint32_t dbase = sb + buf * BUFSZ + g * OPSZ;
#pragma unroll
        for (int i = 0; i < 8; i++) {
            int idx = lt + 64 * i;       // 0..511
            int row = idx >> 2;
            int seg = idx & 3;
            cp_async16(dbase + row * ROWB + seg * 16,
                       opsrc + (size_t)row * K + c * BKC + seg * 8);
        }
        cp_commit();
    };

    float acc[2][8][4];
#pragma unroll
    for (int im = 0; im < 2; im++)
#pragma unroll
        for (int jn = 0; jn < 8; jn++)
#pragma unroll
            for (int r = 0; r < 4; r++) acc[im][jn][r] = 0.f;

    const int at_tile = lane >> 3;
    const int a_row = (at_tile & 1) * 8 + (lane & 7);
    const int a_cadd = (at_tile >> 1) * 16;
    const int b_row = ((at_tile >> 1) * 8) + (lane & 7);
    const int b_cadd = (at_tile & 1) * 16;

    issue_chunk(0, 0);

    for (int c = 0; c < nchunks; c++) {
        const int buf = c & 1;
        cp_wait<0>();
        __syncthreads();
        if (c + 1 < nchunks) issue_chunk(c + 1, buf ^ 1);

        const uint32_t base = sb + buf * BUFSZ;
#pragma unroll
        for (int kk = 0; kk < 2; kk++) {
            const int kb = kk * 32;  // 16 elems = 32 bytes
            uint32_t ah[2][4], al[2][4];
#pragma unroll
            for (int im = 0; im < 2; im++) {
                uint32_t aoff = (uint32_t)(wm * 32 + im * 16 + a_row) * ROWB + kb + a_cadd;
                ldm_x4(ah[im][0], ah[im][1], ah[im][2], ah[im][3], base + 0 * OPSZ + aoff);
                ldm_x4(al[im][0], al[im][1], al[im][2], al[im][3], base + 1 * OPSZ + aoff);
            }
#pragma unroll
            for (int p = 0; p < 4; p++) {
                uint32_t bh4[4], bl4[4];
                uint32_t boff = (uint32_t)(wn * 64 + p * 16 + b_row) * ROWB + kb + b_cadd;
                ldm_x4(bh4[0], bh4[1], bh4[2], bh4[3], base + 2 * OPSZ + boff);
                ldm_x4(bl4[0], bl4[1], bl4[2], bl4[3], base + 3 * OPSZ + boff);
#pragma unroll
                for (int im = 0; im < 2; im++) {
#pragma unroll
                    for (int q2 = 0; q2 < 2; q2++) {
                        const int jn = p * 2 + q2;
                        const int q = q2 * 2;
                        float* cc = acc[im][jn];
                        mma_bf16(cc[0], cc[1], cc[2], cc[3],
                                 ah[im][0], ah[im][1], ah[im][2], ah[im][3],
                                 bh4[q], bh4[q + 1]);
                        mma_bf16(cc[0], cc[1], cc[2], cc[3],
                                 ah[im][0], ah[im][1], ah[im][2], ah[im][3],
                                 bl4[q], bl4[q + 1]);
                        mma_bf16(cc[0], cc[1], cc[2], cc[3],
                                 al[im][0], al[im][1], al[im][2], al[im][3],
                                 bh4[q], bh4[q + 1]);
                    }
                }
            }
        }
    }

    // ---- epilogue
    const int m0 = mtile * 128 + wm * 32;
    const int n0 = ntile * 128 + wn * 64;
#pragma unroll
    for (int im = 0; im < 2; im++) {
#pragma unroll
        for (int jn = 0; jn < 8; jn++) {
            const int row = m0 + im * 16 + (lane >> 2);
            const int col = n0 + jn * 8 + (lane & 3) * 2;
            float b0 = bias ? bias[col] : 0.f;
            float b1 = bias ? bias[col + 1] : 0.f;
            float2 v0 = {acc[im][jn][0] + b0, acc[im][jn][1] + b1};
            float2 v1 = {acc[im][jn][2] + b0, acc[im][jn][3] + b1};
            *reinterpret_cast<float2*>(C + (size_t)row * N + col) = v0;
            *reinterpret_cast<float2*>(C + (size_t)(row + 8) * N + col) = v1;
        }
    }
}

__global__ __launch_bounds__(256, 2) void gemm_bf16x3_kernel(
    const __nv_bfloat16* __restrict__ Ah, const __nv_bfloat16* __restrict__ Al,
    const __nv_bfloat16* __restrict__ Bth, const __nv_bfloat16* __restrict__ Btl,
    float* __restrict__ C, const float* __restrict__ bias, int N, int K, int ntile0)
{
    extern __shared__ char smem[];
    gemm_body(smem, blockIdx.y, blockIdx.x + ntile0, Ah, Al, Bth, Btl, C, bias, N, K);
}

// ---------------------------------------------------------------------------
// kv partial body: kv[d][e] = sum_n k[n,d]*v[n,e], 4-stage cp.async pipeline.
// ---------------------------------------------------------------------------
#define KVCH 16
#define KVST 4

__device__ __forceinline__ void kv_body(char* smem, int bh, int split)
{
    const int b = bh / HEADS, h = bh % HEADS;
    const int n0 = split * (NTOK / NSPLIT);
    const int nstages = (NTOK / NSPLIT) / KVCH;   // 16

    float (*ks)[KVCH][DHEAD] = (float (*)[KVCH][DHEAD])smem;
    float (*vs)[KVCH][DHEAD] = (float (*)[KVCH][DHEAD])(smem + KVST * KVCH * DHEAD * 4);

    const int tid = threadIdx.x;
    const int tx = tid % 16, ty = tid / 16;

    const float* base = g_qkv + (size_t)b * NTOK * QKVN;

    const int li = tid * 4;
    const int lr = li / DHEAD, lc = li % DHEAD;
    uint32_t ks_a[KVST], vs_a[KVST];
#pragma unroll
    for (int s = 0; s < KVST; s++) {
        ks_a[s] = smem_u32(&ks[s][lr][lc]);
        vs_a[s] = smem_u32(&vs[s][lr][lc]);
    }

    auto issue = [&](int s, int buf) {
        const float* p = base + (size_t)(n0 + s * KVCH + lr) * QKVN + h * DHEAD + lc;
        cp_async16(ks_a[buf], p + INNER);
        cp_async16(vs_a[buf], p + 2 * INNER);
        cp_commit();
    };

    float acc[4][4];
#pragma unroll
    for (int i = 0; i < 4; i++)
#pragma unroll
        for (int j = 0; j < 4; j++) acc[i][j] = 0.f;

    issue(0, 0); issue(1, 1); issue(2, 2);

    for (int s = 0; s < nstages; s++) {
        const int buf = s & 3;
        const int ahead = nstages - 1 - s;
        if (ahead >= 2)      cp_wait<2>();
        else if (ahead == 1) cp_wait<1>();
        else                 cp_wait<0>();
        __syncthreads();
        if (s + 3 < nstages) issue(s + 3, (s + 3) & 3);

#pragma unroll
        for (int nn = 0; nn < KVCH; nn++) {
            float rk[4], rv[4];
#pragma unroll
            for (int i = 0; i < 4; i++) rk[i] = ks[buf][nn][ty * 4 + i];
#pragma unroll
            for (int j = 0; j < 4; j++) rv[j] = vs[buf][nn][tx * 4 + j];
#pragma unroll
            for (int i = 0; i < 4; i++)
#pragma unroll
                for (int j = 0; j < 4; j++)
                    acc[i][j] += rk[i] * rv[j];
        }
    }

    float* out = g_part + ((size_t)split * BATCH * HEADS + bh) * (DHEAD * DHEAD);
#pragma unroll
    for (int i = 0; i < 4; i++)
#pragma unroll
        for (int j = 0; j < 4; j++)
            out[(ty * 4 + i) * DHEAD + tx * 4 + j] = acc[i][j];
}

// ---------------------------------------------------------------------------
// packBt body: fp32 W[K][N] -> hi/lo bf16 Bt[N][K]. One 32x32 tile per idx.
// ---------------------------------------------------------------------------
__device__ __forceinline__ void packbt_body(
    char* smem, const float* __restrict__ W,
    __nv_bfloat16* __restrict__ H, __nv_bfloat16* __restrict__ L,
    int idx, int N, int K)
{
    float (*tile)[33] = (float (*)[33])smem;
    const int k0 = (idx & 31) * 32;
    const int n0 = (idx >> 5) * 32;
    const int x = threadIdx.x & 31, y = threadIdx.x >> 5;  // 32 x 8

#pragma unroll
    for (int r = 0; r < 4; r++) {
        int row = y + r * 8;
        tile[row][x] = W[(size_t)(k0 + row) * N + n0 + x];
    }
    __syncthreads();
#pragma unroll
    for (int r = 0; r < 4; r++) {
        int n = y + r * 8;
        float f = tile[x][n];
        ushort h, l;
        split_bf16(f, h, l);
        size_t o = (size_t)(n0 + n) * K + k0 + x;
        H[o] = __ushort_as_bfloat16(h);
        L[o] = __ushort_as_bfloat16(l);
    }
}

// ---------------------------------------------------------------------------
// Fused dispatch: q-GEMM tiles (1024) + kv_partial blocks (1024) + W_o pack (1024)
// ---------------------------------------------------------------------------
__global__ __launch_bounds__(256, 2) void fused_q_kv_packwo_kernel(const float* __restrict__ W_o)
{
    extern __shared__ char smem[];
    const int bx = blockIdx.x;
    if (bx < 1024) {
        gemm_body(smem, bx >> 3, bx & 7, g_xh, g_xl, g_wqh, g_wql,
                  g_qkv, nullptr, QKVN, DIM);
    } else if (bx < 2048) {
        const int i = bx - 1024;
        kv_body(smem, i >> 4, i & 15);
    } else {
        packbt_body(smem, W_o, g_woh, g_wol, bx - 2048, INNER, DIM);
    }
}

// ---------------------------------------------------------------------------
// packA: fp32 [M][K] -> hi/lo bf16 [M][K] (row-major). 8 elems/thread.
// ---------------------------------------------------------------------------
__global__ __launch_bounds__(256) void packA_kernel(
    const float* __restrict__ A, __nv_bfloat16* __restrict__ H,
    __nv_bfloat16* __restrict__ L)
{
    const size_t e0 = ((size_t)blockIdx.x * 256 + threadIdx.x) * 8;
    float4 v0 = *reinterpret_cast<const float4*>(A + e0);
    float4 v1 = *reinterpret_cast<const float4*>(A + e0 + 4);
    float f[8] = {v0.x, v0.y, v0.z, v0.w, v1.x, v1.y, v1.z, v1.w};
    ushort h[8], l[8];
#pragma unroll
    for (int i = 0; i < 8; i++) split_bf16(f[i], h[i], l[i]);
    *reinterpret_cast<uint4*>(H + e0) = *reinterpret_cast<uint4*>(h);
    *reinterpret_cast<uint4*>(L + e0) = *reinterpret_cast<uint4*>(l);
}

// ---------------------------------------------------------------------------
// packBt standalone (for W_qkv)
// ---------------------------------------------------------------------------
__global__ __launch_bounds__(256) void packBt_kernel(
    const float* __restrict__ W, __nv_bfloat16* __restrict__ H,
    __nv_bfloat16* __restrict__ L, int N, int K)
{
    __shared__ float tilebuf[32 * 33];
    const int idx = blockIdx.x + blockIdx.y * 32;   // (k-tile, n-tile)
    packbt_body((char*)tilebuf, W, H, L, ((idx >> 5) << 5) | (idx & 31), N, K);
}

// ---------------------------------------------------------------------------
// kv finalize: C[d][e] = gamma_h^2 * kv[d][e] / ||kv[d,:]||
// ---------------------------------------------------------------------------
__global__ void kv_finalize_kernel(const float* __restrict__ gamma)
{
    const int bh = blockIdx.x;
    const int d = threadIdx.x;
    const int h = bh % HEADS;

    float row[DHEAD];
#pragma unroll
    for (int e = 0; e < DHEAD; e++) row[e] = 0.f;

    for (int s = 0; s < NSPLIT; s++) {
        const float* p = g_part + ((size_t)s * BATCH * HEADS + bh) * (DHEAD * DHEAD) + d * DHEAD;
#pragma unroll
        for (int e = 0; e < DHEAD; e++) row[e] += p[e];
    }
    float ss = 0.f;
#pragma unroll
    for (int e = 0; e < DHEAD; e++) ss += row[e] * row[e];

    const float g = gamma[h];
    const float scale = g * g / sqrtf(ss);

    float* out = g_C + (size_t)bh * DHEAD * DHEAD + d * DHEAD;
#pragma unroll
    for (int e = 0; e < DHEAD; e++) out[e] = row[e] * scale;
}

// ---------------------------------------------------------------------------
// apply: u = (q @ C) / ||q||, emits bf16 hi/lo streams for GEMM2 directly.
// ---------------------------------------------------------------------------
#define QPAD 68

__global__ __launch_bounds__(256) void apply_kernel(
    __nv_bfloat16* __restrict__ UH, __nv_bfloat16* __restrict__ UL)
{
    const int bh = blockIdx.x;
    const int chunk = blockIdx.y;
    const int b = bh / HEADS, h = bh % HEADS;

    __shared__ float Cs[DHEAD][DHEAD];
    __shared__ float qs[64][QPAD];
    __shared__ float inv[64];

    const int tid = threadIdx.x;
    const int n0 = chunk * 64;

#pragma unroll
    for (int i = tid * 4; i < DHEAD * DHEAD; i += 1024)
        *reinterpret_cast<float4*>(&Cs[0][0] + i) =
            *reinterpret_cast<const float4*>(g_C + (size_t)bh * DHEAD * DHEAD + i);

#pragma unroll
    for (int i = tid * 4; i < 64 * DHEAD; i += 1024) {
        int t = i / DHEAD, d = i % DHEAD;
        *reinterpret_cast<float4*>(&qs[t][d]) =
            *reinterpret_cast<const float4*>(g_qkv + (size_t)(b * NTOK + n0 + t) * QKVN + h * DHEAD + d);
    }
    __syncthreads();

    if (tid < 64) {
        float ss = 0.f;
#pragma unroll
        for (int d = 0; d < DHEAD; d++) { float x = qs[tid][d]; ss += x * x; }
        inv[tid] = 1.0f / sqrtf(ss);
    }
    __syncthreads();

    const int tx = tid % 16, ty = tid / 16;
    float acc[4][4];
#pragma unroll
    for (int i = 0; i < 4; i++)
#pragma unroll
        for (int j = 0; j < 4; j++) acc[i][j] = 0.f;

#pragma unroll
    for (int d = 0; d < DHEAD; d++) {
        float rq[4], rc[4];
#pragma unroll
        for (int i = 0; i < 4; i++) rq[i] = qs[ty * 4 + i][d];
#pragma unroll
        for (int j = 0; j < 4; j++) rc[j] = Cs[d][tx * 4 + j];
#pragma unroll
        for (int i = 0; i < 4; i++)
#pragma unroll
            for (int j = 0; j < 4; j++)
                acc[i][j] += rq[i] * rc[j];
    }

#pragma unroll
    for (int i = 0; i < 4; i++) {
        int t = ty * 4 + i;
        float s = inv[t];
        ushort hh[4], ll[4];
#pragma unroll
        for (int j = 0; j < 4; j++) split_bf16(acc[i][j] * s, hh[j], ll[j]);
        size_t o = (size_t)(b * NTOK + n0 + t) * INNER + h * DHEAD + tx * 4;
        *reinterpret_cast<uint2*>(UH + o) = *reinterpret_cast<uint2*>(hh);
        *reinterpret_cast<uint2*>(UL + o) = *reinterpret_cast<uint2*>(ll);
    }
}

// ---------------------------------------------------------------------------
extern "C" void kernel_launch(void* const* d_in, const int* in_sizes, int n_in,
                              void* d_out, int out_size)
{
    const float* x     = (const float*)d_in[0];
    const float* W_qkv = (const float*)d_in[1];
    const float* W_o   = (const float*)d_in[2];
    const float* b_o   = (const float*)d_in[3];
    const float* gamma = (const float*)d_in[4];
    float* out = (float*)d_out;

    static float* qkv_p = nullptr;
    static __nv_bfloat16 *xh, *xl, *uh, *ul, *wqh, *wql, *woh, *wol;
    if (!qkv_p) {
        cudaGetSymbolAddress((void**)&qkv_p, g_qkv);
        cudaGetSymbolAddress((void**)&xh, g_xh);
        cudaGetSymbolAddress((void**)&xl, g_xl);
        cudaGetSymbolAddress((void**)&uh, g_uh);
        cudaGetSymbolAddress((void**)&ul, g_ul);
        cudaGetSymbolAddress((void**)&wqh, g_wqh);
        cudaGetSymbolAddress((void**)&wql, g_wql);
        cudaGetSymbolAddress((void**)&woh, g_woh);
        cudaGetSymbolAddress((void**)&wol, g_wol);
        cudaFuncSetAttribute(gemm_bf16x3_kernel,
                             cudaFuncAttributeMaxDynamicSharedMemorySize, GEMM_SMEM);
        cudaFuncSetAttribute(fused_q_kv_packwo_kernel,
                             cudaFuncAttributeMaxDynamicSharedMemorySize, GEMM_SMEM);
    }

    // 1) pack x and W_qkv
    packA_kernel<<<(size_t)MTOT * DIM / 2048, 256>>>(x, xh, xl);
    packBt_kernel<<<dim3(DIM / 32, QKVN / 32), 256>>>(W_qkv, wqh, wql, QKVN, DIM);

    // 2) k,v columns of qkv = x @ W_qkv  (ntiles 8..23)
    gemm_bf16x3_kernel<<<dim3(16, MTOT / 128), 256, GEMM_SMEM>>>(
        xh, xl, wqh, wql, qkv_p, nullptr, QKVN, DIM, 8);

    // 3) fused: q columns (ntiles 0..7) + kv partials + W_o pack
    fused_q_kv_packwo_kernel<<<3072, 256, GEMM_SMEM>>>(W_o);

    // 4) finalize + apply (apply emits packed u directly)
    kv_finalize_kernel<<<BATCH * HEADS, DHEAD>>>(gamma);
    apply_kernel<<<dim3(BATCH * HEADS, NTOK / 64), 256>>>(uh, ul);

    // 5) out = u @ W_o + b_o
    gemm_bf16x3_kernel<<<dim3(8, MTOT / 128), 256, GEMM_SMEM>>>(
        uh, ul, woh, wol, out, b_o, INNER, DIM, 0);
}

// round 13
// speedup vs baseline: 1.4548x; 1.3498x over previous
#include <cuda_runtime.h>
#include <cuda_bf16.h>
#include <math.h>
#include <stdint.h>

#define DIM     1024
#define HEADS   16
#define DHEAD   64
#define INNER   1024
#define BATCH   4
#define NTOK    4096
#define MTOT    (BATCH * NTOK)      // 16384
#define QKVN    (3 * INNER)         // 3072

// ---------------------------------------------------------------------------
// Scratch (device globals; no runtime allocation allowed)
// ---------------------------------------------------------------------------
__device__ float g_q[(size_t)MTOT * INNER];            // q = x @ Wq          (67 MB)
__device__ float g_T[(size_t)BATCH * DIM * INNER];     // T = G @ Wv          (17 MB)
__device__ float g_C[(size_t)BATCH * HEADS * DHEAD * DHEAD];

__device__ __nv_bfloat16 g_xh[(size_t)MTOT * DIM];     // x row-major h/l
__device__ __nv_bfloat16 g_xl[(size_t)MTOT * DIM];
__device__ __nv_bfloat16 g_xth[(size_t)BATCH * DIM * NTOK];  // x^T per batch h/l
__device__ __nv_bfloat16 g_xtl[(size_t)BATCH * DIM * NTOK];
__device__ __nv_bfloat16 g_uh[(size_t)MTOT * DIM];
__device__ __nv_bfloat16 g_ul[(size_t)MTOT * DIM];
__device__ __nv_bfloat16 g_wqh[(size_t)INNER * DIM];   // Wq^T [N][K]
__device__ __nv_bfloat16 g_wql[(size_t)INNER * DIM];
__device__ __nv_bfloat16 g_wvh[(size_t)INNER * DIM];   // Wv^T [N][K]
__device__ __nv_bfloat16 g_wvl[(size_t)INNER * DIM];
__device__ __nv_bfloat16 g_woh[(size_t)INNER * DIM];   // Wo^T [N][K]
__device__ __nv_bfloat16 g_wol[(size_t)INNER * DIM];
__device__ __nv_bfloat16 g_Gh[(size_t)BATCH * DIM * DIM];  // G = x^T x  h/l
__device__ __nv_bfloat16 g_Gl[(size_t)BATCH * DIM * DIM];

// ---------------------------------------------------------------------------
// helpers
// ---------------------------------------------------------------------------
__device__ __forceinline__ uint32_t smem_u32(const void* p) {
    uint32_t a;
    asm("{ .reg .u64 t; cvta.to.shared.u64 t, %1; cvt.u32.u64 %0, t; }"
        : "=r"(a) : "l"(p));
    return a;
}

__device__ __forceinline__ void cp_async16(uint32_t dst, const void* src) {
    asm volatile("cp.async.cg.shared.global [%0], [%1], 16;"
                 :: "r"(dst), "l"(src) : "memory");
}
__device__ __forceinline__ void cp_commit() {
    asm volatile("cp.async.commit_group;" ::: "memory");
}
template <int N>
__device__ __forceinline__ void cp_wait() {
    asm volatile("cp.async.wait_group %0;" :: "n"(N) : "memory");
}

__device__ __forceinline__ void ldm_x4(uint32_t& r0, uint32_t& r1,
                                       uint32_t& r2, uint32_t& r3, uint32_t a) {
    asm volatile("ldmatrix.sync.aligned.m8n8.x4.shared.b16 {%0,%1,%2,%3}, [%4];"
                 : "=r"(r0), "=r"(r1), "=r"(r2), "=r"(r3) : "r"(a));
}

__device__ __forceinline__ void mma_bf16(float& c0, float& c1, float& c2, float& c3,
                                         uint32_t a0, uint32_t a1, uint32_t a2, uint32_t a3,
                                         uint32_t b0, uint32_t b1) {
    asm volatile(
        "mma.sync.aligned.m16n8k16.row.col.f32.bf16.bf16.f32 "
        "{%0,%1,%2,%3}, {%4,%5,%6,%7}, {%8,%9}, {%0,%1,%2,%3};"
        : "+f"(c0), "+f"(c1), "+f"(c2), "+f"(c3)
        : "r"(a0), "r"(a1), "r"(a2), "r"(a3), "r"(b0), "r"(b1));
}

__device__ __forceinline__ void split_bf16(float f, ushort& h, ushort& l) {
    __nv_bfloat16 hi = __float2bfloat16(f);
    __nv_bfloat16 lo = __float2bfloat16(f - __bfloat162float(hi));
    h = __bfloat16_as_ushort(hi);
    l = __bfloat16_as_ushort(lo);
}

// ---------------------------------------------------------------------------
// GEMM mainloop macro-body pieces. CTA tile 128x128, BK=32, 8 warps (4m x 2n).
// ---------------------------------------------------------------------------
#define BKC      32
#define ROWB     80                      // padded row bytes (40 bf16)
#define OPSZ     (128 * ROWB)            // 10240 B per operand tile
#define BUFSZ    (4 * OPSZ)              // 40960 B per buffer
#define GEMM_SMEM (2 * BUFSZ)            // 81920 B

// Runs the K loop, leaves results in acc[2][8][4]. Shared by both epilogues.
#define GEMM_MAINLOOP(Ah_, Al_, Bth_, Btl_, K_)                                \
    const uint32_t sb = smem_u32(smem);                                        \
    const int tid = threadIdx.x;                                               \
    const int lane = tid & 31;                                                 \
    const int wid = tid >> 5;                                                  \
    const int wm = wid & 3;                                                    \
    const int wn = wid >> 2;                                                   \
    const int g = tid >> 6;                                                    \
    const int lt = tid & 63;                                                   \
    const __nv_bfloat16* opsrc;                                                \
    if (g == 0)      opsrc = (Ah_)  + (size_t)mtile * 128 * (K_);              \
    else if (g == 1) opsrc = (Al_)  + (size_t)mtile * 128 * (K_);              \
    else if (g == 2) opsrc = (Bth_) + (size_t)ntile * 128 * (K_);              \
    else             opsrc = (Btl_) + (size_t)ntile * 128 * (K_);              \
    const int nchunks = (K_) / BKC;                                            \
    auto issue_chunk = [&](int c, int buf) {                                   \
        const uint32_t dbase = sb + buf * BUFSZ + g * OPSZ;                    \
        _Pragma("unroll")                                                      \
        for (int i = 0; i < 8; i++) {                                          \
            int idx = lt + 64 * i;                                             \
            int row = idx >> 2;                                                \
            int seg = idx & 3;                                                 \
            cp_async16(dbase + row * ROWB + seg * 16,                          \
                       opsrc + (size_t)row * (K_) + c * BKC + seg * 8);        \
        }                                                                      \
        cp_commit();                                                           \
    };                                                                         \
    float acc[2][8][4];                                                        \
    _Pragma("unroll")                                                          \
    for (int im = 0; im < 2; im++)                                             \
        _Pragma("unroll")                                                      \
        for (int jn = 0; jn < 8; jn++)                                         \
            _Pragma("unroll")                                                  \
            for (int r = 0; r < 4; r++) acc[im][jn][r] = 0.f;                  \
    const int at_tile = lane >> 3;                                             \
    const int a_row = (at_tile & 1) * 8 + (lane & 7);                          \
    const int a_cadd = (at_tile >> 1) * 16;                                    \
    const int b_row = ((at_tile >> 1) * 8) + (lane & 7);                       \
    const int b_cadd = (at_tile & 1) * 16;                                     \
    issue_chunk(0, 0);                                                         \
    for (int c = 0; c < nchunks; c++) {                                        \
        const int buf = c & 1;                                                 \
        cp_wait<0>();                                                          \
        __syncthreads();                                                       \
        if (c + 1 < nchunks) issue_chunk(c + 1, buf ^ 1);                      \
        const uint32_t base = sb + buf * BUFSZ;                                \
        _Pragma("unroll")                                                      \
        for (int kk = 0; kk < 2; kk++) {                                       \
            const int kb = kk * 32;                                            \
            uint32_t ah[2][4], al[2][4];                                       \
            _Pragma("unroll")                                                  \
            for (int im = 0; im < 2; im++) {                                   \
                uint32_t aoff = (uint32_t)(wm * 32 + im * 16 + a_row) * ROWB + kb + a_cadd; \
                ldm_x4(ah[im][0], ah[im][1], ah[im][2], ah[im][3], base + 0 * OPSZ + aoff); \
                ldm_x4(al[im][0], al[im][1], al[im][2], al[im][3], base + 1 * OPSZ + aoff); \
            }                                                                  \
            _Pragma("unroll")                                                  \
            for (int p = 0; p < 4; p++) {                                      \
                uint32_t bh4[4], bl4[4];                                       \
                uint32_t boff = (uint32_t)(wn * 64 + p * 16 + b_row) * ROWB + kb + b_cadd; \
                ldm_x4(bh4[0], bh4[1], bh4[2], bh4[3], base + 2 * OPSZ + boff);\
                ldm_x4(bl4[0], bl4[1], bl4[2], bl4[3], base + 3 * OPSZ + boff);\
                _Pragma("unroll")                                              \
                for (int im = 0; im < 2; im++) {                               \
                    _Pragma("unroll")                                          \
                    for (int q2 = 0; q2 < 2; q2++) {                           \
                        const int jn = p * 2 + q2;                             \
                        const int q = q2 * 2;                                  \
                        float* cc = acc[im][jn];                               \
                        mma_bf16(cc[0], cc[1], cc[2], cc[3],                   \
                                 ah[im][0], ah[im][1], ah[im][2], ah[im][3],   \
                                 bh4[q], bh4[q + 1]);                          \
                        mma_bf16(cc[0], cc[1], cc[2], cc[3],                   \
                                 ah[im][0], ah[im][1], ah[im][2], ah[im][3],   \
                                 bl4[q], bl4[q + 1]);                          \
                        mma_bf16(cc[0], cc[1], cc[2], cc[3],                   \
                                 al[im][0], al[im][1], al[im][2], al[im][3],   \
                                 bh4[q], bh4[q + 1]);                          \
                    }                                                          \
                }                                                              \
            }                                                                  \
        }                                                                      \
    }

// Standard fp32 epilogue
__device__ __forceinline__ void gemm_body(
    char* smem, int mtile, int ntile,
    const __nv_bfloat16* __restrict__ Ah, const __nv_bfloat16* __restrict__ Al,
    const __nv_bfloat16* __restrict__ Bth, const __nv_bfloat16* __restrict__ Btl,
    float* __restrict__ C, const float* __restrict__ bias, int N, int K)
{
    GEMM_MAINLOOP(Ah, Al, Bth, Btl, K)
    const int m0 = mtile * 128 + wm * 32;
    const int n0 = ntile * 128 + wn * 64;
#pragma unroll
    for (int im = 0; im < 2; im++) {
#pragma unroll
        for (int jn = 0; jn < 8; jn++) {
            const int row = m0 + im * 16 + (lane >> 2);
            const int col = n0 + jn * 8 + (lane & 3) * 2;
            float b0 = bias ? bias[col] : 0.f;
            float b1 = bias ? bias[col + 1] : 0.f;
            float2 v0 = {acc[im][jn][0] + b0, acc[im][jn][1] + b1};
            float2 v1 = {acc[im][jn][2] + b0, acc[im][jn][3] + b1};
            *reinterpret_cast<float2*>(C + (size_t)row * N + col) = v0;
            *reinterpret_cast<float2*>(C + (size_t)(row + 8) * N + col) = v1;
        }
    }
}

// Symmetric-G epilogue: emit bf16 h/l at [row][col] and mirror [col][row]
__device__ __forceinline__ void gemm_sym_body(char* smem, int batch, int mtile, int ntile)
{
    const __nv_bfloat16* Abase = g_xth + (size_t)batch * DIM * NTOK;
    const __nv_bfloat16* Albase = g_xtl + (size_t)batch * DIM * NTOK;
    GEMM_MAINLOOP(Abase, Albase, Abase, Albase, NTOK)
    const int m0 = mtile * 128 + wm * 32;
    const int n0 = ntile * 128 + wn * 64;
    __nv_bfloat16* GH = g_Gh + (size_t)batch * DIM * DIM;
    __nv_bfloat16* GL = g_Gl + (size_t)batch * DIM * DIM;
    const bool mir = (mtile != ntile);
#pragma unroll
    for (int im = 0; im < 2; im++) {
#pragma unroll
        for (int jn = 0; jn < 8; jn++) {
            const int row = m0 + im * 16 + (lane >> 2);
            const int col = n0 + jn * 8 + (lane & 3) * 2;
            ushort h0, l0, h1, l1, h2, l2, h3, l3;
            split_bf16(acc[im][jn][0], h0, l0);
            split_bf16(acc[im][jn][1], h1, l1);
            split_bf16(acc[im][jn][2], h2, l2);
            split_bf16(acc[im][jn][3], h3, l3);
            *reinterpret_cast<uint32_t*>(GH + (size_t)row * DIM + col) =
                (uint32_t)h0 | ((uint32_t)h1 << 16);
            *reinterpret_cast<uint32_t*>(GL + (size_t)row * DIM + col) =
                (uint32_t)l0 | ((uint32_t)l1 << 16);
            *reinterpret_cast<uint32_t*>(GH + (size_t)(row + 8) * DIM + col) =
                (uint32_t)h2 | ((uint32_t)h3 << 16);
            *reinterpret_cast<uint32_t*>(GL + (size_t)(row + 8) * DIM + col) =
                (uint32_t)l2 | ((uint32_t)l3 << 16);
            if (mir) {
                GH[(size_t)col * DIM + row]           = __ushort_as_bfloat16(h0);
                GH[(size_t)(col + 1) * DIM + row]     = __ushort_as_bfloat16(h1);
                GH[(size_t)col * DIM + row + 8]       = __ushort_as_bfloat16(h2);
                GH[(size_t)(col + 1) * DIM + row + 8] = __ushort_as_bfloat16(h3);
                GL[(size_t)col * DIM + row]           = __ushort_as_bfloat16(l0);
                GL[(size_t)(col + 1) * DIM + row]     = __ushort_as_bfloat16(l1);
                GL[(size_t)col * DIM + row + 8]       = __ushort_as_bfloat16(l2);
                GL[(size_t)(col + 1) * DIM + row + 8] = __ushort_as_bfloat16(l3);
            }
        }
    }
}

// Generic GEMM kernel (used for T-GEMM and GEMM2)
__global__ __launch_bounds__(256, 2) void gemm_bf16x3_kernel(
    const __nv_bfloat16* __restrict__ Ah, const __nv_bfloat16* __restrict__ Al,
    const __nv_bfloat16* __restrict__ Bth, const __nv_bfloat16* __restrict__ Btl,
    float* __restrict__ C, const float* __restrict__ bias, int N, int K)
{
    extern __shared__ char smem[];
    gemm_body(smem, blockIdx.y, blockIdx.x, Ah, Al, Bth, Btl, C, bias, N, K);
}

// Kernel A: G-GEMM lower tiles (blocks 0..143, 4x work, scheduled first)
//           + q-GEMM tiles (blocks 144..1167)
__global__ __launch_bounds__(256, 2) void kernelA()
{
    extern __shared__ char smem[];
    const int bx = blockIdx.x;
    if (bx < 144) {
        const int batch = bx / 36, t = bx % 36;
        int mt = 0;
        while ((mt + 1) * (mt + 2) / 2 <= t) mt++;
        const int nt = t - mt * (mt + 1) / 2;
        gemm_sym_body(smem, batch, mt, nt);
    } else {
        const int i = bx - 144;      // 0..1023
        gemm_body(smem, i >> 3, i & 7, g_xh, g_xl, g_wqh, g_wql,
                  g_q, nullptr, INNER, DIM);
    }
}

// ---------------------------------------------------------------------------
// Stage-1 packs: packA(x), packXt(x), packBt(Wq), packBt(Wv), packBt(Wo)
// ---------------------------------------------------------------------------
__device__ __forceinline__ void packbt_g(
    float (*tile)[33], const float* __restrict__ W, int ldW, int col0,
    __nv_bfloat16* __restrict__ H, __nv_bfloat16* __restrict__ L,
    size_t outbase, int Kout, int kt, int nt)
{
    const int k0 = kt * 32, n0 = nt * 32;
    const int x = threadIdx.x & 31, y = threadIdx.x >> 5;  // 32 x 8

#pragma unroll
    for (int r = 0; r < 4; r++) {
        int row = y + r * 8;
        tile[row][x] = W[(size_t)(k0 + row) * ldW + col0 + n0 + x];
    }
    __syncthreads();
#pragma unroll
    for (int r = 0; r < 4; r++) {
        int n = y + r * 8;
        float f = tile[x][n];
        ushort h, l;
        split_bf16(f, h, l);
        size_t o = outbase + (size_t)(n0 + n) * Kout + k0 + x;
        H[o] = __ushort_as_bfloat16(h);
        L[o] = __ushort_as_bfloat16(l);
    }
}

__global__ __launch_bounds__(256) void pack_stage1(
    const float* __restrict__ x, const float* __restrict__ W_qkv,
    const float* __restrict__ W_o)
{
    __shared__ float tile[32][33];
    const int bx = blockIdx.x;
    if (bx < 8192) {
        // packA: x -> g_xh/g_xl row-major
        const size_t e0 = ((size_t)bx * 256 + threadIdx.x) * 8;
        float4 v0 = *reinterpret_cast<const float4*>(x + e0);
        float4 v1 = *reinterpret_cast<const float4*>(x + e0 + 4);
        float f[8] = {v0.x, v0.y, v0.z, v0.w, v1.x, v1.y, v1.z, v1.w};
        ushort h[8], l[8];
#pragma unroll
        for (int i = 0; i < 8; i++) split_bf16(f[i], h[i], l[i]);
        *reinterpret_cast<uint4*>(g_xh + e0) = *reinterpret_cast<uint4*>(h);
        *reinterpret_cast<uint4*>(g_xl + e0) = *reinterpret_cast<uint4*>(l);
    } else if (bx < 24576) {
        // packXt: x_b [4096][1024] -> xt_b [1024][4096]
        const int i = bx - 8192;
        const int batch = i >> 12;          // /4096
        const int t = i & 4095;
        const int kt = t & 127, nt = t >> 7;
        packbt_g(tile, x + (size_t)batch * NTOK * DIM, DIM, 0,
                 g_xth, g_xtl, (size_t)batch * DIM * NTOK, NTOK, kt, nt);
    } else if (bx < 25600) {
        const int t = bx - 24576;
        packbt_g(tile, W_qkv, QKVN, 0, g_wqh, g_wql, 0, DIM, t & 31, t >> 5);
    } else if (bx < 26624) {
        const int t = bx - 25600;
        packbt_g(tile, W_qkv, QKVN, 2 * INNER, g_wvh, g_wvl, 0, DIM, t & 31, t >> 5);
    } else {
        const int t = bx - 26624;
        packbt_g(tile, W_o, INNER, 0, g_woh, g_wol, 0, DIM, t & 31, t >> 5);
    }
}

// ---------------------------------------------------------------------------
// finalize: kv_bh = Wk_h^T @ T_bh  (fp32, K=1024), then row-normalize * gamma^2
// ---------------------------------------------------------------------------
#define FCH 16

__global__ __launch_bounds__(256) void kv_finalize_kernel(
    const float* __restrict__ W_qkv, const float* __restrict__ gamma)
{
    const int bh = blockIdx.x;
    const int b = bh >> 4, h = bh & 15;

    __shared__ float wks[2][FCH][DHEAD];
    __shared__ float ts[2][FCH][DHEAD];
    __shared__ float red[64][17];
    __shared__ float inv[64];

    const int tid = threadIdx.x;
    const int tx = tid % 16, ty = tid / 16;
    const int lr = tid >> 4, lc = (tid * 4) & 63;

    const uint32_t wk_a[2] = {smem_u32(&wks[0][lr][lc]), smem_u32(&wks[1][lr][lc])};
    const uint32_t ts_a[2] = {smem_u32(&ts[0][lr][lc]), smem_u32(&ts[1][lr][lc])};

    auto issue = [&](int s, int buf) {
        const float* wp = W_qkv + (size_t)(s * FCH + lr) * QKVN + INNER + h * DHEAD + lc;
        const float* tp = g_T + ((size_t)b * DIM + s * FCH + lr) * INNER + h * DHEAD + lc;
        cp_async16(wk_a[buf], wp);
        cp_async16(ts_a[buf], tp);
        cp_commit();
    };

    float acc[4][4];
#pragma unroll
    for (int i = 0; i < 4; i++)
#pragma unroll
        for (int j = 0; j < 4; j++) acc[i][j] = 0.f;

    const int nst = DIM / FCH;   // 64
    issue(0, 0);
    for (int s = 0; s < nst; s++) {
        const int buf = s & 1;
        if (s + 1 < nst) { issue(s + 1, buf ^ 1); cp_wait<1>(); }
        else             { cp_wait<0>(); }
        __syncthreads();
#pragma unroll
        for (int nn = 0; nn < FCH; nn++) {
            float rk[4], rv[4];
#pragma unroll
            for (int i = 0; i < 4; i++) rk[i] = wks[buf][nn][ty * 4 + i];
#pragma unroll
            for (int j = 0; j < 4; j++) rv[j] = ts[buf][nn][tx * 4 + j];
#pragma unroll
            for (int i = 0; i < 4; i++)
#pragma unroll
                for (int j = 0; j < 4; j++)
                    acc[i][j] += rk[i] * rv[j];
        }
        __syncthreads();
    }

    // row-norm reduction
#pragma unroll
    for (int i = 0; i < 4; i++)
        red[ty * 4 + i][tx] = acc[i][0] * acc[i][0] + acc[i][1] * acc[i][1] +
                              acc[i][2] * acc[i][2] + acc[i][3] * acc[i][3];
    __syncthreads();
    if (tid < 64) {
        float s = 0.f;
#pragma unroll
        for (int t = 0; t < 16; t++) s += red[tid][t];
        const float gm = gamma[h];
        inv[tid] = gm * gm / sqrtf(s);
    }
    __syncthreads();

    float* out = g_C + (size_t)bh * DHEAD * DHEAD;
#pragma unroll
    for (int i = 0; i < 4; i++) {
        const float sc = inv[ty * 4 + i];
#pragma unroll
        for (int j = 0; j < 4; j++)
            out[(ty * 4 + i) * DHEAD + tx * 4 + j] = acc[i][j] * sc;
    }
}

// ---------------------------------------------------------------------------
// apply: u = (q @ C) / ||q||, emits bf16 hi/lo streams for GEMM2 directly.
// ---------------------------------------------------------------------------
#define QPAD 68

__global__ __launch_bounds__(256) void apply_kernel(
    __nv_bfloat16* __restrict__ UH, __nv_bfloat16* __restrict__ UL)
{
    const int bh = blockIdx.x;
    const int chunk = blockIdx.y;
    const int b = bh / HEADS, h = bh % HEADS;

    __shared__ float Cs[DHEAD][DHEAD];
    __shared__ float qs[64][QPAD];
    __shared__ float inv[64];

    const int tid = threadIdx.x;
    const int n0 = chunk * 64;

#pragma unroll
    for (int i = tid * 4; i < DHEAD * DHEAD; i += 1024)
        *reinterpret_cast<float4*>(&Cs[0][0] + i) =
            *reinterpret_cast<const float4*>(g_C + (size_t)bh * DHEAD * DHEAD + i);

#pragma unroll
    for (int i = tid * 4; i < 64 * DHEAD; i += 1024) {
        int t = i / DHEAD, d = i % DHEAD;
        *reinterpret_cast<float4*>(&qs[t][d]) =
            *reinterpret_cast<const float4*>(g_q + (size_t)(b * NTOK + n0 + t) * INNER + h * DHEAD + d);
    }
    __syncthreads();

    if (tid < 64) {
        float ss = 0.f;
#pragma unroll
        for (int d = 0; d < DHEAD; d++) { float v = qs[tid][d]; ss += v * v; }
        inv[tid] = 1.0f / sqrtf(ss);
    }
    __syncthreads();

    const int tx = tid % 16, ty = tid / 16;
    float acc[4][4];
#pragma unroll
    for (int i = 0; i < 4; i++)
#pragma unroll
        for (int j = 0; j < 4; j++) acc[i][j] = 0.f;

#pragma unroll
    for (int d = 0; d < DHEAD; d++) {
        float rq[4], rc[4];
#pragma unroll
        for (int i = 0; i < 4; i++) rq[i] = qs[ty * 4 + i][d];
#pragma unroll
        for (int j = 0; j < 4; j++) rc[j] = Cs[d][tx * 4 + j];
#pragma unroll
        for (int i = 0; i < 4; i++)
#pragma unroll
            for (int j = 0; j < 4; j++)
                acc[i][j] += rq[i] * rc[j];
    }

#pragma unroll
    for (int i = 0; i < 4; i++) {
        int t = ty * 4 + i;
        float s = inv[t];
        ushort hh[4], ll[4];
#pragma unroll
        for (int j = 0; j < 4; j++) split_bf16(acc[i][j] * s, hh[j], ll[j]);
        size_t o = (size_t)(b * NTOK + n0 + t) * INNER + h * DHEAD + tx * 4;
        *reinterpret_cast<uint2*>(UH + o) = *reinterpret_cast<uint2*>(hh);
        *reinterpret_cast<uint2*>(UL + o) = *reinterpret_cast<uint2*>(ll);
    }
}

// ---------------------------------------------------------------------------
extern "C" void kernel_launch(void* const* d_in, const int* in_sizes, int n_in,
                              void* d_out, int out_size)
{
    const float* x     = (const float*)d_in[0];
    const float* W_qkv = (const float*)d_in[1];
    const float* W_o   = (const float*)d_in[2];
    const float* b_o   = (const float*)d_in[3];
    const float* gamma = (const float*)d_in[4];
    float* out = (float*)d_out;

    static float* T_p = nullptr;
    static __nv_bfloat16 *uh, *ul, *woh, *wol, *wvh, *wvl, *Gh, *Gl;
    if (!T_p) {
        cudaGetSymbolAddress((void**)&T_p, g_T);
        cudaGetSymbolAddress((void**)&uh, g_uh);
        cudaGetSymbolAddress((void**)&ul, g_ul);
        cudaGetSymbolAddress((void**)&woh, g_woh);
        cudaGetSymbolAddress((void**)&wol, g_wol);
        cudaGetSymbolAddress((void**)&wvh, g_wvh);
        cudaGetSymbolAddress((void**)&wvl, g_wvl);
        cudaGetSymbolAddress((void**)&Gh, g_Gh);
        cudaGetSymbolAddress((void**)&Gl, g_Gl);
        cudaFuncSetAttribute(gemm_bf16x3_kernel,
                             cudaFuncAttributeMaxDynamicSharedMemorySize, GEMM_SMEM);
        cudaFuncSetAttribute(kernelA,
                             cudaFuncAttributeMaxDynamicSharedMemorySize, GEMM_SMEM);
    }

    // 1) all packs: x (row + transposed), Wq, Wv, Wo
    pack_stage1<<<27648, 256>>>(x, W_qkv, W_o);

    // 2) G = x^T x (lower tiles, 4x-long blocks first) + q = x @ Wq
    kernelA<<<1168, 256, GEMM_SMEM>>>();

    // 3) T = G @ Wv   [4096 x 1024], K=1024
    gemm_bf16x3_kernel<<<dim3(8, 32), 256, GEMM_SMEM>>>(
        Gh, Gl, wvh, wvl, T_p, nullptr, INNER, DIM);

    // 4) kv = Wk^T T per (b,h), normalize, fold gamma^2 -> C
    kv_finalize_kernel<<<BATCH * HEADS, 256>>>(W_qkv, gamma);

    // 5) u = (q/||q||) @ C  (emits bf16 h/l)
    apply_kernel<<<dim3(BATCH * HEADS, NTOK / 64), 256>>>(uh, ul);

    // 6) out = u @ W_o + b_o
    gemm_bf16x3_kernel<<<dim3(8, 128), 256, GEMM_SMEM>>>(
        uh, ul, woh, wol, out, b_o, INNER, DIM);
}